// round 1
// baseline (speedup 1.0000x reference)
#include <cuda_runtime.h>
#include <cuda_bf16.h>

// ---------------------------------------------------------------------------
// Problem shape (fixed): B=4, N=2048, D=1024, H=16, Hd=64.
// scores sum over ALL (h,d) -> single-head attention over D=1024, scale 1/8.
//
// Pipeline:
//  1) QKV[8192,3072] = x[8192,1024] @ w_qkv^T            (NT gemm)
//  2) S[b][2048,2048] = Q[b] @ K[b]^T * 0.125            (NT gemm, batched)
//  3) softmax rows of S
//  4) O[b][2048,1024] = S[b] @ V[b]                      (NN gemm, batched)
//  5) out[8192,1024] = O @ w_out^T + b_out               (NT gemm, bias)
// ---------------------------------------------------------------------------

#define BM 128
#define BN 128
#define BK 16

// Scratch (device globals: allocation-guard safe).
__device__ float g_qkv[8192ull * 3072];      // 96 MB
__device__ float g_S[4ull * 2048 * 2048];    // 64 MB
__device__ float g_O[8192ull * 1024];        // 32 MB

// ---------------------------------------------------------------------------
// NT GEMM: C[m,n] = alpha * sum_k A[m,k]*B[n,k] (+ bias[n])
// A: [M,K] row-major (lda), B: [N,K] row-major (ldb), C: [M,N] (ldc).
// Grid: (N/BN, M/BM, batch). 256 threads; 8x8 per thread as 2x2 quads of 4x4.
// ---------------------------------------------------------------------------
__global__ void __launch_bounds__(256)
gemm_nt(const float* __restrict__ A, const float* __restrict__ B,
        float* __restrict__ C, const float* __restrict__ bias,
        int lda, int ldb, int ldc, int K, float alpha,
        long long sA, long long sB, long long sC)
{
    A += (long long)blockIdx.z * sA;
    B += (long long)blockIdx.z * sB;
    C += (long long)blockIdx.z * sC;

    __shared__ float As[BK][BM];
    __shared__ float Bs[BK][BN];

    const int tid = threadIdx.x;
    const int tx  = tid & 15;
    const int ty  = tid >> 4;
    const int tx4 = tx * 4;
    const int ty4 = ty * 4;
    const int row0 = blockIdx.y * BM;
    const int col0 = blockIdx.x * BN;

    float acc[2][2][4][4];
#pragma unroll
    for (int a = 0; a < 2; a++)
#pragma unroll
        for (int b = 0; b < 2; b++)
#pragma unroll
            for (int i = 0; i < 4; i++)
#pragma unroll
                for (int j = 0; j < 4; j++)
                    acc[a][b][i][j] = 0.0f;

    for (int kb = 0; kb < K; kb += BK) {
#pragma unroll
        for (int it = 0; it < 2; it++) {
            int f  = tid + it * 256;
            int r  = f >> 2;             // 0..127
            int c4 = (f & 3) * 4;        // 0,4,8,12
            float4 va = *(const float4*)(A + (size_t)(row0 + r) * lda + kb + c4);
            As[c4 + 0][r] = va.x;
            As[c4 + 1][r] = va.y;
            As[c4 + 2][r] = va.z;
            As[c4 + 3][r] = va.w;
            float4 vb = *(const float4*)(B + (size_t)(col0 + r) * ldb + kb + c4);
            Bs[c4 + 0][r] = vb.x;
            Bs[c4 + 1][r] = vb.y;
            Bs[c4 + 2][r] = vb.z;
            Bs[c4 + 3][r] = vb.w;
        }
        __syncthreads();

#pragma unroll
        for (int kk = 0; kk < BK; kk++) {
            float4 a0 = *(const float4*)&As[kk][ty4];
            float4 a1 = *(const float4*)&As[kk][ty4 + 64];
            float4 b0 = *(const float4*)&Bs[kk][tx4];
            float4 b1 = *(const float4*)&Bs[kk][tx4 + 64];
            float av[2][4] = {{a0.x, a0.y, a0.z, a0.w}, {a1.x, a1.y, a1.z, a1.w}};
            float bv[2][4] = {{b0.x, b0.y, b0.z, b0.w}, {b1.x, b1.y, b1.z, b1.w}};
#pragma unroll
            for (int ri = 0; ri < 2; ri++)
#pragma unroll
                for (int ci = 0; ci < 2; ci++)
#pragma unroll
                    for (int i = 0; i < 4; i++)
#pragma unroll
                        for (int j = 0; j < 4; j++)
                            acc[ri][ci][i][j] += av[ri][i] * bv[ci][j];
        }
        __syncthreads();
    }

#pragma unroll
    for (int ri = 0; ri < 2; ri++) {
        int rbase = row0 + ri * 64 + ty4;
#pragma unroll
        for (int i = 0; i < 4; i++) {
            int r = rbase + i;
#pragma unroll
            for (int ci = 0; ci < 2; ci++) {
                int c = col0 + ci * 64 + tx4;
                float4 o;
                o.x = alpha * acc[ri][ci][i][0];
                o.y = alpha * acc[ri][ci][i][1];
                o.z = alpha * acc[ri][ci][i][2];
                o.w = alpha * acc[ri][ci][i][3];
                if (bias) {
                    o.x += bias[c + 0];
                    o.y += bias[c + 1];
                    o.z += bias[c + 2];
                    o.w += bias[c + 3];
                }
                *(float4*)(C + (size_t)r * ldc + c) = o;
            }
        }
    }
}

// ---------------------------------------------------------------------------
// NN GEMM: C[m,n] = alpha * sum_k A[m,k]*B[k,n]
// A: [M,K] row-major (lda), B: [K,N] row-major (ldb).
// ---------------------------------------------------------------------------
__global__ void __launch_bounds__(256)
gemm_nn(const float* __restrict__ A, const float* __restrict__ B,
        float* __restrict__ C,
        int lda, int ldb, int ldc, int K, float alpha,
        long long sA, long long sB, long long sC)
{
    A += (long long)blockIdx.z * sA;
    B += (long long)blockIdx.z * sB;
    C += (long long)blockIdx.z * sC;

    __shared__ float As[BK][BM];
    __shared__ float Bs[BK][BN];

    const int tid = threadIdx.x;
    const int tx  = tid & 15;
    const int ty  = tid >> 4;
    const int tx4 = tx * 4;
    const int ty4 = ty * 4;
    const int row0 = blockIdx.y * BM;
    const int col0 = blockIdx.x * BN;

    float acc[2][2][4][4];
#pragma unroll
    for (int a = 0; a < 2; a++)
#pragma unroll
        for (int b = 0; b < 2; b++)
#pragma unroll
            for (int i = 0; i < 4; i++)
#pragma unroll
                for (int j = 0; j < 4; j++)
                    acc[a][b][i][j] = 0.0f;

    for (int kb = 0; kb < K; kb += BK) {
#pragma unroll
        for (int it = 0; it < 2; it++) {
            int f  = tid + it * 256;
            // A tile: 128 rows x 16 cols
            int r  = f >> 2;
            int c4 = (f & 3) * 4;
            float4 va = *(const float4*)(A + (size_t)(row0 + r) * lda + kb + c4);
            As[c4 + 0][r] = va.x;
            As[c4 + 1][r] = va.y;
            As[c4 + 2][r] = va.z;
            As[c4 + 3][r] = va.w;
            // B tile: 16 rows x 128 cols, direct (coalesced, conflict-free)
            int br  = f >> 5;            // 0..15
            int bc4 = (f & 31) * 4;      // 0..124
            float4 vb = *(const float4*)(B + (size_t)(kb + br) * ldb + col0 + bc4);
            *(float4*)&Bs[br][bc4] = vb;
        }
        __syncthreads();

#pragma unroll
        for (int kk = 0; kk < BK; kk++) {
            float4 a0 = *(const float4*)&As[kk][ty4];
            float4 a1 = *(const float4*)&As[kk][ty4 + 64];
            float4 b0 = *(const float4*)&Bs[kk][tx4];
            float4 b1 = *(const float4*)&Bs[kk][tx4 + 64];
            float av[2][4] = {{a0.x, a0.y, a0.z, a0.w}, {a1.x, a1.y, a1.z, a1.w}};
            float bv[2][4] = {{b0.x, b0.y, b0.z, b0.w}, {b1.x, b1.y, b1.z, b1.w}};
#pragma unroll
            for (int ri = 0; ri < 2; ri++)
#pragma unroll
                for (int ci = 0; ci < 2; ci++)
#pragma unroll
                    for (int i = 0; i < 4; i++)
#pragma unroll
                        for (int j = 0; j < 4; j++)
                            acc[ri][ci][i][j] += av[ri][i] * bv[ci][j];
        }
        __syncthreads();
    }

#pragma unroll
    for (int ri = 0; ri < 2; ri++) {
        int rbase = row0 + ri * 64 + ty4;
#pragma unroll
        for (int i = 0; i < 4; i++) {
            int r = rbase + i;
#pragma unroll
            for (int ci = 0; ci < 2; ci++) {
                int c = col0 + ci * 64 + tx4;
                float4 o;
                o.x = alpha * acc[ri][ci][i][0];
                o.y = alpha * acc[ri][ci][i][1];
                o.z = alpha * acc[ri][ci][i][2];
                o.w = alpha * acc[ri][ci][i][3];
                *(float4*)(C + (size_t)r * ldc + c) = o;
            }
        }
    }
}

// ---------------------------------------------------------------------------
// Row softmax over 2048-wide rows. One block (256 threads) per row.
// ---------------------------------------------------------------------------
__global__ void __launch_bounds__(256)
softmax_rows(float* __restrict__ S)
{
    float* row = S + (size_t)blockIdx.x * 2048;
    const int tid = threadIdx.x;

    float v[8];
    float m = -1e30f;
#pragma unroll
    for (int i = 0; i < 8; i++) {
        v[i] = row[tid + 256 * i];
        m = fmaxf(m, v[i]);
    }

    __shared__ float red[8];
#pragma unroll
    for (int o = 16; o; o >>= 1) m = fmaxf(m, __shfl_xor_sync(0xffffffffu, m, o));
    if ((tid & 31) == 0) red[tid >> 5] = m;
    __syncthreads();
    m = red[0];
#pragma unroll
    for (int i = 1; i < 8; i++) m = fmaxf(m, red[i]);
    __syncthreads();   // before reusing red[]

    float s = 0.0f;
#pragma unroll
    for (int i = 0; i < 8; i++) {
        v[i] = __expf(v[i] - m);
        s += v[i];
    }
#pragma unroll
    for (int o = 16; o; o >>= 1) s += __shfl_xor_sync(0xffffffffu, s, o);
    if ((tid & 31) == 0) red[tid >> 5] = s;
    __syncthreads();
    s = 0.0f;
#pragma unroll
    for (int i = 0; i < 8; i++) s += red[i];

    float inv = 1.0f / s;
#pragma unroll
    for (int i = 0; i < 8; i++) row[tid + 256 * i] = v[i] * inv;
}

// ---------------------------------------------------------------------------
extern "C" void kernel_launch(void* const* d_in, const int* in_sizes, int n_in,
                              void* d_out, int out_size)
{
    (void)in_sizes; (void)n_in; (void)out_size;
    const float* x     = (const float*)d_in[0];   // [4,2048,1024]
    const float* w_qkv = (const float*)d_in[1];   // [3072,1024]
    const float* w_out = (const float*)d_in[2];   // [1024,1024]
    const float* b_out = (const float*)d_in[3];   // [1024]
    float* out = (float*)d_out;                   // [4,2048,1024]

    float *qkv, *S, *O;
    cudaGetSymbolAddress((void**)&qkv, g_qkv);
    cudaGetSymbolAddress((void**)&S,   g_S);
    cudaGetSymbolAddress((void**)&O,   g_O);

    // 1) QKV = x @ w_qkv^T : M=8192, N=3072, K=1024
    gemm_nt<<<dim3(3072 / BN, 8192 / BM, 1), 256>>>(
        x, w_qkv, qkv, nullptr,
        1024, 1024, 3072, 1024, 1.0f, 0, 0, 0);

    // 2) S[b] = Q[b] @ K[b]^T * 0.125 : M=N=2048, K=1024, batch=4
    gemm_nt<<<dim3(2048 / BN, 2048 / BM, 4), 256>>>(
        qkv, qkv + 1024, S, nullptr,
        3072, 3072, 2048, 1024, 0.125f,
        2048ll * 3072, 2048ll * 3072, 2048ll * 2048);

    // 3) softmax rows (4*2048 rows of 2048)
    softmax_rows<<<4 * 2048, 256>>>(S);

    // 4) O[b] = S[b] @ V[b] : M=2048, N=1024, K=2048, batch=4
    gemm_nn<<<dim3(1024 / BN, 2048 / BM, 4), 256>>>(
        S, qkv + 2048, O,
        2048, 3072, 1024, 2048, 1.0f,
        2048ll * 2048, 2048ll * 3072, 2048ll * 1024);

    // 5) out = O @ w_out^T + b_out : M=8192, N=1024, K=1024
    gemm_nt<<<dim3(1024 / BN, 8192 / BM, 1), 256>>>(
        O, w_out, out, b_out,
        1024, 1024, 1024, 1024, 1.0f, 0, 0, 0);
}

// round 3
// speedup vs baseline: 1.7898x; 1.7898x over previous
#include <cuda_runtime.h>
#include <cuda_bf16.h>
#include <cstdint>

// ---------------------------------------------------------------------------
// B=4, N=2048, D=1024. scores sum over (h,d) -> single-head attn over 1024.
// All GEMMs on tensor cores via 3-term bf16 split:
//   x ≈ xh + xl (bf16 each);  A·B ≈ Ah·Bh + Ah·Bl + Al·Bh  (fp32 accum)
// Error per product ~2^-18 — far below the 1e-3 harness threshold.
// Pipeline:
//  0) split x, w_qkv, w_out into (hi,lo) bf16
//  1) QKV = x @ w_qkv^T            -> split qkv (hi,lo)
//  2) S[b] = Q[b] @ K[b]^T * .125  -> fp32 S
//  3) softmax rows                 -> split probs (hi,lo)
//  4) Vt[b] = V[b]^T               -> split Vt
//  5) O[b] = S[b] @ Vt[b]^T (NT)   -> split O
//  6) out = O @ w_out^T + b_out    -> fp32 out
// ---------------------------------------------------------------------------

#define BM 128
#define BN 128
#define BK 32
#define STAGES 3
#define LDT2 40                               // bf16 elems per smem row (pad 8)
#define TILE_BYTES (128 * LDT2 * 2)           // 10240 B
#define STAGE_BYTES (4 * TILE_BYTES)          // Ah, Al, Bh, Bl = 40960 B
#define SMEM_BYTES (STAGES * STAGE_BYTES)     // 122880 B

// ---------------- scratch (device globals: allocation-guard safe) ----------
__device__ __align__(256) float         g_S[4ull * 2048 * 2048];     // 64 MB
__device__ __align__(256) __nv_bfloat16 g_xh[8192ull * 1024];
__device__ __align__(256) __nv_bfloat16 g_xl[8192ull * 1024];
__device__ __align__(256) __nv_bfloat16 g_wqh[3072ull * 1024];
__device__ __align__(256) __nv_bfloat16 g_wql[3072ull * 1024];
__device__ __align__(256) __nv_bfloat16 g_woh[1024ull * 1024];
__device__ __align__(256) __nv_bfloat16 g_wol[1024ull * 1024];
__device__ __align__(256) __nv_bfloat16 g_qkvh[8192ull * 3072];
__device__ __align__(256) __nv_bfloat16 g_qkvl[8192ull * 3072];
__device__ __align__(256) __nv_bfloat16 g_Sh[4ull * 2048 * 2048];
__device__ __align__(256) __nv_bfloat16 g_Sl[4ull * 2048 * 2048];
__device__ __align__(256) __nv_bfloat16 g_Vth[4ull * 1024 * 2048];
__device__ __align__(256) __nv_bfloat16 g_Vtl[4ull * 1024 * 2048];
__device__ __align__(256) __nv_bfloat16 g_Oh[8192ull * 1024];
__device__ __align__(256) __nv_bfloat16 g_Ol[8192ull * 1024];

// ---------------------------------------------------------------------------
__device__ __forceinline__ uint32_t s2u(const void* p) {
    uint32_t a;
    asm("{ .reg .u64 t; cvta.to.shared.u64 t, %1; cvt.u32.u64 %0, t; }"
        : "=r"(a) : "l"(p));
    return a;
}

__device__ __forceinline__ void cp16(uint32_t dst, const void* src) {
    asm volatile("cp.async.cg.shared.global [%0], [%1], 16;" :: "r"(dst), "l"(src));
}

__device__ __forceinline__ void ldm4(uint32_t* r, uint32_t addr) {
    asm volatile("ldmatrix.sync.aligned.m8n8.x4.shared.b16 {%0,%1,%2,%3}, [%4];"
        : "=r"(r[0]), "=r"(r[1]), "=r"(r[2]), "=r"(r[3]) : "r"(addr));
}

__device__ __forceinline__ void mma_bf16(float* c, const uint32_t* a,
                                         uint32_t b0, uint32_t b1) {
    asm volatile(
        "mma.sync.aligned.m16n8k16.row.col.f32.bf16.bf16.f32 "
        "{%0,%1,%2,%3}, {%4,%5,%6,%7}, {%8,%9}, {%0,%1,%2,%3};"
        : "+f"(c[0]), "+f"(c[1]), "+f"(c[2]), "+f"(c[3])
        : "r"(a[0]), "r"(a[1]), "r"(a[2]), "r"(a[3]), "r"(b0), "r"(b1));
}

__device__ __forceinline__ void split1(float x, __nv_bfloat16& h, __nv_bfloat16& l) {
    h = __float2bfloat16_rn(x);
    l = __float2bfloat16_rn(x - __bfloat162float(h));
}

// ---------------------------------------------------------------------------
// fp32 -> (hi, lo) bf16 split, vectorized.
__global__ void __launch_bounds__(256)
split_kernel(const float4* __restrict__ in,
             __nv_bfloat162* __restrict__ h, __nv_bfloat162* __restrict__ l, int n4)
{
    int i = blockIdx.x * blockDim.x + threadIdx.x;
    if (i < n4) {
        float4 v = in[i];
        __nv_bfloat16 hx, hy, hz, hw, lx, ly, lz, lw;
        split1(v.x, hx, lx); split1(v.y, hy, ly);
        split1(v.z, hz, lz); split1(v.w, hw, lw);
        h[2 * i]     = __nv_bfloat162(hx, hy);
        h[2 * i + 1] = __nv_bfloat162(hz, hw);
        l[2 * i]     = __nv_bfloat162(lx, ly);
        l[2 * i + 1] = __nv_bfloat162(lz, lw);
    }
}

// ---------------------------------------------------------------------------
// Vt[b][d][n] = V[b][n][d]  for hi and lo components (V = qkv cols 2048..3071)
__global__ void __launch_bounds__(256)
transpose_v(const __nv_bfloat16* __restrict__ qh, const __nv_bfloat16* __restrict__ ql,
            __nv_bfloat16* __restrict__ Vth, __nv_bfloat16* __restrict__ Vtl)
{
    __shared__ __nv_bfloat16 th[32][34], tl[32][34];
    int b  = blockIdx.z;
    int n0 = blockIdx.x * 32;
    int d0 = blockIdx.y * 32;
    int tx = threadIdx.x, ty = threadIdx.y;   // 32 x 8
    const __nv_bfloat16* Vh = qh + (size_t)b * 2048 * 3072 + 2048;
    const __nv_bfloat16* Vl = ql + (size_t)b * 2048 * 3072 + 2048;
#pragma unroll
    for (int i = 0; i < 32; i += 8) {
        th[ty + i][tx] = Vh[(size_t)(n0 + ty + i) * 3072 + d0 + tx];
        tl[ty + i][tx] = Vl[(size_t)(n0 + ty + i) * 3072 + d0 + tx];
    }
    __syncthreads();
    __nv_bfloat16* dh = Vth + (size_t)b * 1024 * 2048;
    __nv_bfloat16* dl = Vtl + (size_t)b * 1024 * 2048;
#pragma unroll
    for (int i = 0; i < 32; i += 8) {
        dh[(size_t)(d0 + ty + i) * 2048 + n0 + tx] = th[tx][ty + i];
        dl[(size_t)(d0 + ty + i) * 2048 + n0 + tx] = tl[tx][ty + i];
    }
}

// ---------------------------------------------------------------------------
// Split NT tensor-core GEMM: C = alpha * A B^T (+bias), A [M,K], B [N,K]
// (both given as hi/lo bf16), output either fp32 (Cf) or split bf16 (Ch,Cl).
// Grid (N/BN, M/BM, batch); 256 threads = 8 warps (2 m x 4 n), 64x32 per warp.
// ---------------------------------------------------------------------------
__global__ void __launch_bounds__(256)
gemm_nt_split(const __nv_bfloat16* __restrict__ Ah, const __nv_bfloat16* __restrict__ Al,
              const __nv_bfloat16* __restrict__ Bh, const __nv_bfloat16* __restrict__ Bl,
              float* __restrict__ Cf,
              __nv_bfloat16* __restrict__ Ch, __nv_bfloat16* __restrict__ Cl,
              const float* __restrict__ bias,
              int lda, int ldb, int ldc, int K, float alpha,
              long long sA, long long sB, long long sC)
{
    extern __shared__ char smem[];
    const long long offA = (long long)blockIdx.z * sA;
    const long long offB = (long long)blockIdx.z * sB;
    const long long offC = (long long)blockIdx.z * sC;
    Ah += offA; Al += offA;
    Bh += offB; Bl += offB;

    const int tid  = threadIdx.x;
    const int wid  = tid >> 5, lane = tid & 31;
    const int wm   = wid & 1,  wn   = wid >> 1;
    const int g    = lane >> 2, t   = lane & 3;
    const int row0 = blockIdx.y * BM;
    const int col0 = blockIdx.x * BN;

    const uint32_t smem_u = s2u(smem);

    // loader mapping: 256 threads, each does rows r and r+64, 8 bf16 chunk
    const int lr  = tid >> 2;           // 0..63
    const int lc8 = (tid & 3) * 8;      // 0,8,16,24

    const __nv_bfloat16* Abh = Ah + (size_t)row0 * lda;
    const __nv_bfloat16* Abl = Al + (size_t)row0 * lda;
    const __nv_bfloat16* Bbh = Bh + (size_t)col0 * ldb;
    const __nv_bfloat16* Bbl = Bl + (size_t)col0 * ldb;

    float acc[4][4][4];
#pragma unroll
    for (int i = 0; i < 4; i++)
#pragma unroll
        for (int j = 0; j < 4; j++)
#pragma unroll
            for (int r = 0; r < 4; r++)
                acc[i][j][r] = 0.0f;

    const int nk = K / BK;

    auto load_tile = [&](int kb, int s) {
        uint32_t st  = smem_u + (uint32_t)s * STAGE_BYTES;
        uint32_t tAh = st;
        uint32_t tAl = st + TILE_BYTES;
        uint32_t tBh = st + 2 * TILE_BYTES;
        uint32_t tBl = st + 3 * TILE_BYTES;
        const int kc = kb * BK + lc8;
#pragma unroll
        for (int hh = 0; hh < 2; hh++) {
            int r = lr + hh * 64;
            uint32_t so = (uint32_t)(r * LDT2 + lc8) * 2u;
            cp16(tAh + so, Abh + (size_t)r * lda + kc);
            cp16(tAl + so, Abl + (size_t)r * lda + kc);
            cp16(tBh + so, Bbh + (size_t)r * ldb + kc);
            cp16(tBl + so, Bbl + (size_t)r * ldb + kc);
        }
    };

    load_tile(0, 0);
    asm volatile("cp.async.commit_group;");
    if (nk > 1) load_tile(1, 1);
    asm volatile("cp.async.commit_group;");
    asm volatile("cp.async.wait_group 1;");
    __syncthreads();

    // ldmatrix lane addressing
    const int lrow = lane & 15;
    const int lk   = (lane >> 4) * 8;
    const uint32_t aoff0 = (uint32_t)((wm * 64 + lrow) * LDT2 + lk) * 2u;
    const uint32_t boff0 = (uint32_t)((wn * 32 + lrow) * LDT2 + lk) * 2u;

    for (int kb = 0; kb < nk; kb++) {
        const int cur = kb % STAGES;
        const uint32_t st  = smem_u + (uint32_t)cur * STAGE_BYTES;
        const uint32_t tAh = st + aoff0;
        const uint32_t tAl = st + TILE_BYTES + aoff0;
        const uint32_t tBh = st + 2 * TILE_BYTES + boff0;
        const uint32_t tBl = st + 3 * TILE_BYTES + boff0;

#pragma unroll
        for (int ks = 0; ks < 2; ks++) {
            uint32_t ah[4][4], al[4][4], bh[2][4], bl[2][4];
#pragma unroll
            for (int i = 0; i < 4; i++) {
                uint32_t o = (uint32_t)(i * 16 * LDT2 + ks * 16) * 2u;
                ldm4(ah[i], tAh + o);
                ldm4(al[i], tAl + o);
            }
#pragma unroll
            for (int jp = 0; jp < 2; jp++) {
                uint32_t o = (uint32_t)(jp * 16 * LDT2 + ks * 16) * 2u;
                ldm4(bh[jp], tBh + o);
                ldm4(bl[jp], tBl + o);
            }
#pragma unroll
            for (int i = 0; i < 4; i++)
#pragma unroll
                for (int j = 0; j < 4; j++) {
                    const int jp = j >> 1, sjj = j & 1;
                    mma_bf16(acc[i][j], ah[i], bh[jp][sjj], bh[jp][sjj + 2]);
                    mma_bf16(acc[i][j], ah[i], bl[jp][sjj], bl[jp][sjj + 2]);
                    mma_bf16(acc[i][j], al[i], bh[jp][sjj], bh[jp][sjj + 2]);
                }
        }

        if (kb + 2 < nk) {
            load_tile(kb + 2, (kb + 2) % STAGES);
            asm volatile("cp.async.commit_group;");
            asm volatile("cp.async.wait_group 1;");
        } else {
            asm volatile("cp.async.wait_group 0;");
        }
        __syncthreads();
    }

    // ---- epilogue
#pragma unroll
    for (int i = 0; i < 4; i++) {
        const int r = row0 + wm * 64 + i * 16 + g;
#pragma unroll
        for (int j = 0; j < 4; j++) {
            const int c = col0 + wn * 32 + j * 8 + 2 * t;
            float v[4];
            v[0] = alpha * acc[i][j][0];
            v[1] = alpha * acc[i][j][1];
            v[2] = alpha * acc[i][j][2];
            v[3] = alpha * acc[i][j][3];
            if (bias) {
                float bx = bias[c], by = bias[c + 1];
                v[0] += bx; v[1] += by; v[2] += bx; v[3] += by;
            }
            if (Cf) {
                *(float2*)(Cf + offC + (size_t)r * ldc + c)       = make_float2(v[0], v[1]);
                *(float2*)(Cf + offC + (size_t)(r + 8) * ldc + c) = make_float2(v[2], v[3]);
            }
            if (Ch) {
                __nv_bfloat16 h0, l0, h1, l1, h2, l2, h3, l3;
                split1(v[0], h0, l0); split1(v[1], h1, l1);
                split1(v[2], h2, l2); split1(v[3], h3, l3);
                *(__nv_bfloat162*)(Ch + offC + (size_t)r * ldc + c)       = __nv_bfloat162(h0, h1);
                *(__nv_bfloat162*)(Cl + offC + (size_t)r * ldc + c)       = __nv_bfloat162(l0, l1);
                *(__nv_bfloat162*)(Ch + offC + (size_t)(r + 8) * ldc + c) = __nv_bfloat162(h2, h3);
                *(__nv_bfloat162*)(Cl + offC + (size_t)(r + 8) * ldc + c) = __nv_bfloat162(l2, l3);
            }
        }
    }
}

// ---------------------------------------------------------------------------
// Row softmax over 2048-wide rows; writes split bf16 probs.
__global__ void __launch_bounds__(256)
softmax_split(const float* __restrict__ S,
              __nv_bfloat16* __restrict__ Sh, __nv_bfloat16* __restrict__ Sl)
{
    const size_t base = (size_t)blockIdx.x * 2048;
    const float* row = S + base;
    const int tid = threadIdx.x;

    float v[8];
    float m = -1e30f;
#pragma unroll
    for (int i = 0; i < 8; i++) {
        v[i] = row[tid + 256 * i];
        m = fmaxf(m, v[i]);
    }

    __shared__ float red[8];
#pragma unroll
    for (int o = 16; o; o >>= 1) m = fmaxf(m, __shfl_xor_sync(0xffffffffu, m, o));
    if ((tid & 31) == 0) red[tid >> 5] = m;
    __syncthreads();
    m = red[0];
#pragma unroll
    for (int i = 1; i < 8; i++) m = fmaxf(m, red[i]);
    __syncthreads();

    float s = 0.0f;
#pragma unroll
    for (int i = 0; i < 8; i++) {
        v[i] = __expf(v[i] - m);
        s += v[i];
    }
#pragma unroll
    for (int o = 16; o; o >>= 1) s += __shfl_xor_sync(0xffffffffu, s, o);
    if ((tid & 31) == 0) red[tid >> 5] = s;
    __syncthreads();
    s = 0.0f;
#pragma unroll
    for (int i = 0; i < 8; i++) s += red[i];

    float inv = 1.0f / s;
#pragma unroll
    for (int i = 0; i < 8; i++) {
        float p = v[i] * inv;
        __nv_bfloat16 h, l;
        split1(p, h, l);
        Sh[base + tid + 256 * i] = h;
        Sl[base + tid + 256 * i] = l;
    }
}

// ---------------------------------------------------------------------------
extern "C" void kernel_launch(void* const* d_in, const int* in_sizes, int n_in,
                              void* d_out, int out_size)
{
    (void)in_sizes; (void)n_in; (void)out_size;
    const float* x     = (const float*)d_in[0];   // [4,2048,1024]
    const float* w_qkv = (const float*)d_in[1];   // [3072,1024]
    const float* w_out = (const float*)d_in[2];   // [1024,1024]
    const float* b_out = (const float*)d_in[3];   // [1024]
    float* out = (float*)d_out;                   // [4,2048,1024]

    float* S;
    __nv_bfloat16 *xh, *xl, *wqh, *wql, *woh, *wol, *qkvh, *qkvl;
    __nv_bfloat16 *Sh, *Sl, *Vth, *Vtl, *Oh, *Ol;
    cudaGetSymbolAddress((void**)&S,    g_S);
    cudaGetSymbolAddress((void**)&xh,   g_xh);   cudaGetSymbolAddress((void**)&xl,   g_xl);
    cudaGetSymbolAddress((void**)&wqh,  g_wqh);  cudaGetSymbolAddress((void**)&wql,  g_wql);
    cudaGetSymbolAddress((void**)&woh,  g_woh);  cudaGetSymbolAddress((void**)&wol,  g_wol);
    cudaGetSymbolAddress((void**)&qkvh, g_qkvh); cudaGetSymbolAddress((void**)&qkvl, g_qkvl);
    cudaGetSymbolAddress((void**)&Sh,   g_Sh);   cudaGetSymbolAddress((void**)&Sl,   g_Sl);
    cudaGetSymbolAddress((void**)&Vth,  g_Vth);  cudaGetSymbolAddress((void**)&Vtl,  g_Vtl);
    cudaGetSymbolAddress((void**)&Oh,   g_Oh);   cudaGetSymbolAddress((void**)&Ol,   g_Ol);

    cudaFuncSetAttribute(gemm_nt_split,
                         cudaFuncAttributeMaxDynamicSharedMemorySize, SMEM_BYTES);

    // 0) split inputs
    {
        int n4 = 8192 * 1024 / 4;
        split_kernel<<<(n4 + 255) / 256, 256>>>((const float4*)x,
            (__nv_bfloat162*)xh, (__nv_bfloat162*)xl, n4);
        n4 = 3072 * 1024 / 4;
        split_kernel<<<(n4 + 255) / 256, 256>>>((const float4*)w_qkv,
            (__nv_bfloat162*)wqh, (__nv_bfloat162*)wql, n4);
        n4 = 1024 * 1024 / 4;
        split_kernel<<<(n4 + 255) / 256, 256>>>((const float4*)w_out,
            (__nv_bfloat162*)woh, (__nv_bfloat162*)wol, n4);
    }

    // 1) QKV = x @ w_qkv^T : M=8192, N=3072, K=1024 -> split qkv
    gemm_nt_split<<<dim3(3072 / BN, 8192 / BM, 1), 256, SMEM_BYTES>>>(
        xh, xl, wqh, wql, nullptr, qkvh, qkvl, nullptr,
        1024, 1024, 3072, 1024, 1.0f, 0, 0, 0);

    // 2) S[b] = Q[b] @ K[b]^T * 0.125 : fp32 out
    gemm_nt_split<<<dim3(2048 / BN, 2048 / BM, 4), 256, SMEM_BYTES>>>(
        qkvh, qkvl, qkvh + 1024, qkvl + 1024, S, nullptr, nullptr, nullptr,
        3072, 3072, 2048, 1024, 0.125f,
        2048ll * 3072, 2048ll * 3072, 2048ll * 2048);

    // 3) softmax -> split probs
    softmax_split<<<4 * 2048, 256>>>(S, Sh, Sl);

    // 4) Vt[b] = V[b]^T (hi & lo)
    transpose_v<<<dim3(2048 / 32, 1024 / 32, 4), dim3(32, 8)>>>(qkvh, qkvl, Vth, Vtl);

    // 5) O[b] = S[b] @ V[b] = NT(Sh/Sl, Vth/Vtl) : M=2048, N=1024, K=2048 -> split O
    gemm_nt_split<<<dim3(1024 / BN, 2048 / BM, 4), 256, SMEM_BYTES>>>(
        Sh, Sl, Vth, Vtl, nullptr, Oh, Ol, nullptr,
        2048, 2048, 1024, 2048, 1.0f,
        2048ll * 2048, 1024ll * 2048, 2048ll * 1024);

    // 6) out = O @ w_out^T + b_out : fp32 out
    gemm_nt_split<<<dim3(1024 / BN, 8192 / BM, 1), 256, SMEM_BYTES>>>(
        Oh, Ol, woh, wol, out, nullptr, nullptr, b_out,
        1024, 1024, 1024, 1024, 1.0f, 0, 0, 0);
}

// round 5
// speedup vs baseline: 1.9294x; 1.0779x over previous
#include <cuda_runtime.h>
#include <cuda_bf16.h>
#include <cstdint>

// ---------------------------------------------------------------------------
// B=4, N=2048, D=1024. scores sum over (h,d) -> single-head attn over 1024.
// All GEMMs on tensor cores via 3-term bf16 split:
//   x ≈ xh + xl (bf16 each);  A·B ≈ Ah·Bh + Ah·Bl + Al·Bh  (fp32 accum)
// 2-stage cp.async pipeline, 2 CTAs/SM (smem 80KB, regs 128) for issue overlap.
// ---------------------------------------------------------------------------

#define BM 128
#define BN 128
#define BK 32
#define STAGES 2
#define LDT2 40                               // bf16 elems per smem row (pad 8)
#define TILE_BYTES (128 * LDT2 * 2)           // 10240 B
#define STAGE_BYTES (4 * TILE_BYTES)          // Ah, Al, Bh, Bl = 40960 B
#define SMEM_BYTES (STAGES * STAGE_BYTES)     // 81920 B -> 2 CTAs/SM

// ---------------- scratch (device globals: allocation-guard safe) ----------
__device__ __align__(256) float         g_S[4ull * 2048 * 2048];     // 64 MB
__device__ __align__(256) __nv_bfloat16 g_xh[8192ull * 1024];
__device__ __align__(256) __nv_bfloat16 g_xl[8192ull * 1024];
__device__ __align__(256) __nv_bfloat16 g_wqh[3072ull * 1024];
__device__ __align__(256) __nv_bfloat16 g_wql[3072ull * 1024];
__device__ __align__(256) __nv_bfloat16 g_woh[1024ull * 1024];
__device__ __align__(256) __nv_bfloat16 g_wol[1024ull * 1024];
__device__ __align__(256) __nv_bfloat16 g_qkvh[8192ull * 3072];
__device__ __align__(256) __nv_bfloat16 g_qkvl[8192ull * 3072];
__device__ __align__(256) __nv_bfloat16 g_Sh[4ull * 2048 * 2048];
__device__ __align__(256) __nv_bfloat16 g_Sl[4ull * 2048 * 2048];
__device__ __align__(256) __nv_bfloat16 g_Vth[4ull * 1024 * 2048];
__device__ __align__(256) __nv_bfloat16 g_Vtl[4ull * 1024 * 2048];
__device__ __align__(256) __nv_bfloat16 g_Oh[8192ull * 1024];
__device__ __align__(256) __nv_bfloat16 g_Ol[8192ull * 1024];

// ---------------------------------------------------------------------------
__device__ __forceinline__ uint32_t s2u(const void* p) {
    uint32_t a;
    asm("{ .reg .u64 t; cvta.to.shared.u64 t, %1; cvt.u32.u64 %0, t; }"
        : "=r"(a) : "l"(p));
    return a;
}

__device__ __forceinline__ void cp16(uint32_t dst, const void* src) {
    asm volatile("cp.async.cg.shared.global [%0], [%1], 16;" :: "r"(dst), "l"(src));
}

__device__ __forceinline__ void ldm4(uint32_t* r, uint32_t addr) {
    asm volatile("ldmatrix.sync.aligned.m8n8.x4.shared.b16 {%0,%1,%2,%3}, [%4];"
        : "=r"(r[0]), "=r"(r[1]), "=r"(r[2]), "=r"(r[3]) : "r"(addr));
}

__device__ __forceinline__ void mma_bf16(float* c, const uint32_t* a,
                                         uint32_t b0, uint32_t b1) {
    asm volatile(
        "mma.sync.aligned.m16n8k16.row.col.f32.bf16.bf16.f32 "
        "{%0,%1,%2,%3}, {%4,%5,%6,%7}, {%8,%9}, {%0,%1,%2,%3};"
        : "+f"(c[0]), "+f"(c[1]), "+f"(c[2]), "+f"(c[3])
        : "r"(a[0]), "r"(a[1]), "r"(a[2]), "r"(a[3]), "r"(b0), "r"(b1));
}

__device__ __forceinline__ void split1(float x, __nv_bfloat16& h, __nv_bfloat16& l) {
    h = __float2bfloat16_rn(x);
    l = __float2bfloat16_rn(x - __bfloat162float(h));
}

// ---------------------------------------------------------------------------
// fp32 -> (hi, lo) bf16 split, vectorized.
__global__ void __launch_bounds__(256)
split_kernel(const float4* __restrict__ in,
             __nv_bfloat162* __restrict__ h, __nv_bfloat162* __restrict__ l, int n4)
{
    int i = blockIdx.x * blockDim.x + threadIdx.x;
    if (i < n4) {
        float4 v = in[i];
        __nv_bfloat16 hx, hy, hz, hw, lx, ly, lz, lw;
        split1(v.x, hx, lx); split1(v.y, hy, ly);
        split1(v.z, hz, lz); split1(v.w, hw, lw);
        h[2 * i]     = __nv_bfloat162(hx, hy);
        h[2 * i + 1] = __nv_bfloat162(hz, hw);
        l[2 * i]     = __nv_bfloat162(lx, ly);
        l[2 * i + 1] = __nv_bfloat162(lz, lw);
    }
}

// ---------------------------------------------------------------------------
// Vt[b][d][n] = V[b][n][d]  for hi and lo components (V = qkv cols 2048..3071)
__global__ void __launch_bounds__(256)
transpose_v(const __nv_bfloat16* __restrict__ qh, const __nv_bfloat16* __restrict__ ql,
            __nv_bfloat16* __restrict__ Vth, __nv_bfloat16* __restrict__ Vtl)
{
    __shared__ __nv_bfloat16 th[32][34], tl[32][34];
    int b  = blockIdx.z;
    int n0 = blockIdx.x * 32;
    int d0 = blockIdx.y * 32;
    int tx = threadIdx.x, ty = threadIdx.y;   // 32 x 8
    const __nv_bfloat16* Vh = qh + (size_t)b * 2048 * 3072 + 2048;
    const __nv_bfloat16* Vl = ql + (size_t)b * 2048 * 3072 + 2048;
#pragma unroll
    for (int i = 0; i < 32; i += 8) {
        th[ty + i][tx] = Vh[(size_t)(n0 + ty + i) * 3072 + d0 + tx];
        tl[ty + i][tx] = Vl[(size_t)(n0 + ty + i) * 3072 + d0 + tx];
    }
    __syncthreads();
    __nv_bfloat16* dh = Vth + (size_t)b * 1024 * 2048;
    __nv_bfloat16* dl = Vtl + (size_t)b * 1024 * 2048;
#pragma unroll
    for (int i = 0; i < 32; i += 8) {
        dh[(size_t)(d0 + ty + i) * 2048 + n0 + tx] = th[tx][ty + i];
        dl[(size_t)(d0 + ty + i) * 2048 + n0 + tx] = tl[tx][ty + i];
    }
}

// ---------------------------------------------------------------------------
// Split NT tensor-core GEMM: C = alpha * A B^T (+bias), A [M,K], B [N,K]
// (both given as hi/lo bf16), output either fp32 (Cf) or split bf16 (Ch,Cl).
// Grid (N/BN, M/BM, batch); 256 threads = 8 warps (2 m x 4 n), 64x32 per warp.
// ---------------------------------------------------------------------------
__global__ void __launch_bounds__(256, 2)
gemm_nt_split(const __nv_bfloat16* __restrict__ Ah, const __nv_bfloat16* __restrict__ Al,
              const __nv_bfloat16* __restrict__ Bh, const __nv_bfloat16* __restrict__ Bl,
              float* __restrict__ Cf,
              __nv_bfloat16* __restrict__ Ch, __nv_bfloat16* __restrict__ Cl,
              const float* __restrict__ bias,
              int lda, int ldb, int ldc, int K, float alpha,
              long long sA, long long sB, long long sC)
{
    extern __shared__ char smem[];
    const long long offA = (long long)blockIdx.z * sA;
    const long long offB = (long long)blockIdx.z * sB;
    const long long offC = (long long)blockIdx.z * sC;
    Ah += offA; Al += offA;
    Bh += offB; Bl += offB;

    const int tid  = threadIdx.x;
    const int wid  = tid >> 5, lane = tid & 31;
    const int wm   = wid & 1,  wn   = wid >> 1;
    const int g    = lane >> 2, t   = lane & 3;
    const int row0 = blockIdx.y * BM;
    const int col0 = blockIdx.x * BN;

    const uint32_t smem_u = s2u(smem);

    // loader mapping: 256 threads, each does rows r and r+64, 8 bf16 chunk
    const int lr  = tid >> 2;           // 0..63
    const int lc8 = (tid & 3) * 8;      // 0,8,16,24

    const __nv_bfloat16* Abh = Ah + (size_t)row0 * lda;
    const __nv_bfloat16* Abl = Al + (size_t)row0 * lda;
    const __nv_bfloat16* Bbh = Bh + (size_t)col0 * ldb;
    const __nv_bfloat16* Bbl = Bl + (size_t)col0 * ldb;

    float acc[4][4][4];
#pragma unroll
    for (int i = 0; i < 4; i++)
#pragma unroll
        for (int j = 0; j < 4; j++)
#pragma unroll
            for (int r = 0; r < 4; r++)
                acc[i][j][r] = 0.0f;

    const int nk = K / BK;

    auto load_tile = [&](int kb, int s) {
        uint32_t st  = smem_u + (uint32_t)s * STAGE_BYTES;
        uint32_t tAh = st;
        uint32_t tAl = st + TILE_BYTES;
        uint32_t tBh = st + 2 * TILE_BYTES;
        uint32_t tBl = st + 3 * TILE_BYTES;
        const int kc = kb * BK + lc8;
#pragma unroll
        for (int hh = 0; hh < 2; hh++) {
            int r = lr + hh * 64;
            uint32_t so = (uint32_t)(r * LDT2 + lc8) * 2u;
            cp16(tAh + so, Abh + (size_t)r * lda + kc);
            cp16(tAl + so, Abl + (size_t)r * lda + kc);
            cp16(tBh + so, Bbh + (size_t)r * ldb + kc);
            cp16(tBl + so, Bbl + (size_t)r * ldb + kc);
        }
    };

    load_tile(0, 0);
    asm volatile("cp.async.commit_group;");
    if (nk > 1) load_tile(1, 1);
    asm volatile("cp.async.commit_group;");

    // ldmatrix lane addressing
    const int lrow = lane & 15;
    const int lk   = (lane >> 4) * 8;
    const uint32_t aoff0 = (uint32_t)((wm * 64 + lrow) * LDT2 + lk) * 2u;
    const uint32_t boff0 = (uint32_t)((wn * 32 + lrow) * LDT2 + lk) * 2u;

    for (int kb = 0; kb < nk; kb++) {
        if (kb + 1 < nk) asm volatile("cp.async.wait_group 1;");
        else             asm volatile("cp.async.wait_group 0;");
        __syncthreads();

        const uint32_t st  = smem_u + (uint32_t)(kb & 1) * STAGE_BYTES;
        const uint32_t tAh = st + aoff0;
        const uint32_t tAl = st + TILE_BYTES + aoff0;
        const uint32_t tBh = st + 2 * TILE_BYTES + boff0;
        const uint32_t tBl = st + 3 * TILE_BYTES + boff0;

#pragma unroll
        for (int ks = 0; ks < 2; ks++) {
            uint32_t ah[4][4], al[4][4], bh[2][4], bl[2][4];
#pragma unroll
            for (int i = 0; i < 4; i++) {
                uint32_t o = (uint32_t)(i * 16 * LDT2 + ks * 16) * 2u;
                ldm4(ah[i], tAh + o);
                ldm4(al[i], tAl + o);
            }
#pragma unroll
            for (int jp = 0; jp < 2; jp++) {
                uint32_t o = (uint32_t)(jp * 16 * LDT2 + ks * 16) * 2u;
                ldm4(bh[jp], tBh + o);
                ldm4(bl[jp], tBl + o);
            }
#pragma unroll
            for (int i = 0; i < 4; i++)
#pragma unroll
                for (int j = 0; j < 4; j++) {
                    const int jp = j >> 1, sjj = j & 1;
                    mma_bf16(acc[i][j], ah[i], bh[jp][sjj], bh[jp][sjj + 2]);
                    mma_bf16(acc[i][j], ah[i], bl[jp][sjj], bl[jp][sjj + 2]);
                    mma_bf16(acc[i][j], al[i], bh[jp][sjj], bh[jp][sjj + 2]);
                }
        }

        __syncthreads();
        if (kb + 2 < nk) {
            load_tile(kb + 2, kb & 1);
            asm volatile("cp.async.commit_group;");
        }
    }

    // ---- epilogue
#pragma unroll
    for (int i = 0; i < 4; i++) {
        const int r = row0 + wm * 64 + i * 16 + g;
#pragma unroll
        for (int j = 0; j < 4; j++) {
            const int c = col0 + wn * 32 + j * 8 + 2 * t;
            float v[4];
            v[0] = alpha * acc[i][j][0];
            v[1] = alpha * acc[i][j][1];
            v[2] = alpha * acc[i][j][2];
            v[3] = alpha * acc[i][j][3];
            if (bias) {
                float bx = bias[c], by = bias[c + 1];
                v[0] += bx; v[1] += by; v[2] += bx; v[3] += by;
            }
            if (Cf) {
                *(float2*)(Cf + offC + (size_t)r * ldc + c)       = make_float2(v[0], v[1]);
                *(float2*)(Cf + offC + (size_t)(r + 8) * ldc + c) = make_float2(v[2], v[3]);
            }
            if (Ch) {
                __nv_bfloat16 h0, l0, h1, l1, h2, l2, h3, l3;
                split1(v[0], h0, l0); split1(v[1], h1, l1);
                split1(v[2], h2, l2); split1(v[3], h3, l3);
                *(__nv_bfloat162*)(Ch + offC + (size_t)r * ldc + c)       = __nv_bfloat162(h0, h1);
                *(__nv_bfloat162*)(Cl + offC + (size_t)r * ldc + c)       = __nv_bfloat162(l0, l1);
                *(__nv_bfloat162*)(Ch + offC + (size_t)(r + 8) * ldc + c) = __nv_bfloat162(h2, h3);
                *(__nv_bfloat162*)(Cl + offC + (size_t)(r + 8) * ldc + c) = __nv_bfloat162(l2, l3);
            }
        }
    }
}

// ---------------------------------------------------------------------------
// Row softmax over 2048-wide rows; writes split bf16 probs.
__global__ void __launch_bounds__(256)
softmax_split(const float* __restrict__ S,
              __nv_bfloat16* __restrict__ Sh, __nv_bfloat16* __restrict__ Sl)
{
    const size_t base = (size_t)blockIdx.x * 2048;
    const float* row = S + base;
    const int tid = threadIdx.x;

    float v[8];
    float m = -1e30f;
#pragma unroll
    for (int i = 0; i < 8; i++) {
        v[i] = row[tid + 256 * i];
        m = fmaxf(m, v[i]);
    }

    __shared__ float red[8];
#pragma unroll
    for (int o = 16; o; o >>= 1) m = fmaxf(m, __shfl_xor_sync(0xffffffffu, m, o));
    if ((tid & 31) == 0) red[tid >> 5] = m;
    __syncthreads();
    m = red[0];
#pragma unroll
    for (int i = 1; i < 8; i++) m = fmaxf(m, red[i]);
    __syncthreads();

    float s = 0.0f;
#pragma unroll
    for (int i = 0; i < 8; i++) {
        v[i] = __expf(v[i] - m);
        s += v[i];
    }
#pragma unroll
    for (int o = 16; o; o >>= 1) s += __shfl_xor_sync(0xffffffffu, s, o);
    if ((tid & 31) == 0) red[tid >> 5] = s;
    __syncthreads();
    s = 0.0f;
#pragma unroll
    for (int i = 0; i < 8; i++) s += red[i];

    float inv = 1.0f / s;
#pragma unroll
    for (int i = 0; i < 8; i++) {
        float p = v[i] * inv;
        __nv_bfloat16 h, l;
        split1(p, h, l);
        Sh[base + tid + 256 * i] = h;
        Sl[base + tid + 256 * i] = l;
    }
}

// ---------------------------------------------------------------------------
extern "C" void kernel_launch(void* const* d_in, const int* in_sizes, int n_in,
                              void* d_out, int out_size)
{
    (void)in_sizes; (void)n_in; (void)out_size;
    const float* x     = (const float*)d_in[0];   // [4,2048,1024]
    const float* w_qkv = (const float*)d_in[1];   // [3072,1024]
    const float* w_out = (const float*)d_in[2];   // [1024,1024]
    const float* b_out = (const float*)d_in[3];   // [1024]
    float* out = (float*)d_out;                   // [4,2048,1024]

    float* S;
    __nv_bfloat16 *xh, *xl, *wqh, *wql, *woh, *wol, *qkvh, *qkvl;
    __nv_bfloat16 *Sh, *Sl, *Vth, *Vtl, *Oh, *Ol;
    cudaGetSymbolAddress((void**)&S,    g_S);
    cudaGetSymbolAddress((void**)&xh,   g_xh);   cudaGetSymbolAddress((void**)&xl,   g_xl);
    cudaGetSymbolAddress((void**)&wqh,  g_wqh);  cudaGetSymbolAddress((void**)&wql,  g_wql);
    cudaGetSymbolAddress((void**)&woh,  g_woh);  cudaGetSymbolAddress((void**)&wol,  g_wol);
    cudaGetSymbolAddress((void**)&qkvh, g_qkvh); cudaGetSymbolAddress((void**)&qkvl, g_qkvl);
    cudaGetSymbolAddress((void**)&Sh,   g_Sh);   cudaGetSymbolAddress((void**)&Sl,   g_Sl);
    cudaGetSymbolAddress((void**)&Vth,  g_Vth);  cudaGetSymbolAddress((void**)&Vtl,  g_Vtl);
    cudaGetSymbolAddress((void**)&Oh,   g_Oh);   cudaGetSymbolAddress((void**)&Ol,   g_Ol);

    cudaFuncSetAttribute(gemm_nt_split,
                         cudaFuncAttributeMaxDynamicSharedMemorySize, SMEM_BYTES);

    // 0) split inputs
    {
        int n4 = 8192 * 1024 / 4;
        split_kernel<<<(n4 + 255) / 256, 256>>>((const float4*)x,
            (__nv_bfloat162*)xh, (__nv_bfloat162*)xl, n4);
        n4 = 3072 * 1024 / 4;
        split_kernel<<<(n4 + 255) / 256, 256>>>((const float4*)w_qkv,
            (__nv_bfloat162*)wqh, (__nv_bfloat162*)wql, n4);
        n4 = 1024 * 1024 / 4;
        split_kernel<<<(n4 + 255) / 256, 256>>>((const float4*)w_out,
            (__nv_bfloat162*)woh, (__nv_bfloat162*)wol, n4);
    }

    // 1) QKV = x @ w_qkv^T : M=8192, N=3072, K=1024 -> split qkv
    gemm_nt_split<<<dim3(3072 / BN, 8192 / BM, 1), 256, SMEM_BYTES>>>(
        xh, xl, wqh, wql, nullptr, qkvh, qkvl, nullptr,
        1024, 1024, 3072, 1024, 1.0f, 0, 0, 0);

    // 2) S[b] = Q[b] @ K[b]^T * 0.125 : fp32 out
    gemm_nt_split<<<dim3(2048 / BN, 2048 / BM, 4), 256, SMEM_BYTES>>>(
        qkvh, qkvl, qkvh + 1024, qkvl + 1024, S, nullptr, nullptr, nullptr,
        3072, 3072, 2048, 1024, 0.125f,
        2048ll * 3072, 2048ll * 3072, 2048ll * 2048);

    // 3) softmax -> split probs
    softmax_split<<<4 * 2048, 256>>>(S, Sh, Sl);

    // 4) Vt[b] = V[b]^T (hi & lo)
    transpose_v<<<dim3(2048 / 32, 1024 / 32, 4), dim3(32, 8)>>>(qkvh, qkvl, Vth, Vtl);

    // 5) O[b] = S[b] @ V[b] = NT(Sh/Sl, Vth/Vtl) : M=2048, N=1024, K=2048 -> split O
    gemm_nt_split<<<dim3(1024 / BN, 2048 / BM, 4), 256, SMEM_BYTES>>>(
        Sh, Sl, Vth, Vtl, nullptr, Oh, Ol, nullptr,
        2048, 2048, 1024, 2048, 1.0f,
        2048ll * 2048, 1024ll * 2048, 2048ll * 1024);

    // 6) out = O @ w_out^T + b_out : fp32 out
    gemm_nt_split<<<dim3(1024 / BN, 8192 / BM, 1), 256, SMEM_BYTES>>>(
        Oh, Ol, woh, wol, out, nullptr, nullptr, b_out,
        1024, 1024, 1024, 1024, 1.0f, 0, 0, 0);
}

// round 6
// speedup vs baseline: 2.7310x; 1.4155x over previous
#include <cuda_runtime.h>
#include <cuda_fp16.h>
#include <cstdint>

// ---------------------------------------------------------------------------
// B=4, N=2048, D=1024. scores sum over (h,d) -> single-head attn over 1024.
// Tensor-core GEMMs via fp16 split:  x = xh + xl (fp16 each, err ~2^-23)
//   3-term:  A·B ≈ Ah·Bh + Ah·Bl + Al·Bh   (QKV, S gemms — full precision)
//   2-term:  A·B ≈ Ah·Bh + Al·Bh = A·Bh    (O, out gemms — err ~1.4e-4 direct)
// 3-stage cp.async pipeline, XOR-swizzled smem (no pad), 2 CTAs/SM, 1 sync/ktile.
// ---------------------------------------------------------------------------

#define BM 128
#define BN 128
#define BK 32
#define TILE_B 8192                     // 128 rows * 64 B (32 fp16, no pad)

// ---------------- scratch (device globals: allocation-guard safe) ----------
__device__ __align__(256) float  g_S[4ull * 2048 * 2048];     // 64 MB
__device__ __align__(256) __half g_xh[8192ull * 1024];
__device__ __align__(256) __half g_xl[8192ull * 1024];
__device__ __align__(256) __half g_wqh[3072ull * 1024];
__device__ __align__(256) __half g_wql[3072ull * 1024];
__device__ __align__(256) __half g_woh[1024ull * 1024];
__device__ __align__(256) __half g_wol[1024ull * 1024];
__device__ __align__(256) __half g_qkvh[8192ull * 3072];
__device__ __align__(256) __half g_qkvl[8192ull * 3072];
__device__ __align__(256) __half g_Sh[4ull * 2048 * 2048];
__device__ __align__(256) __half g_Sl[4ull * 2048 * 2048];
__device__ __align__(256) __half g_Vth[4ull * 1024 * 2048];   // fp16(V)^T
__device__ __align__(256) __half g_Oh[8192ull * 1024];
__device__ __align__(256) __half g_Ol[8192ull * 1024];

// ---------------------------------------------------------------------------
__device__ __forceinline__ uint32_t s2u(const void* p) {
    uint32_t a;
    asm("{ .reg .u64 t; cvta.to.shared.u64 t, %1; cvt.u32.u64 %0, t; }"
        : "=r"(a) : "l"(p));
    return a;
}

__device__ __forceinline__ void cp16(uint32_t dst, const void* src) {
    asm volatile("cp.async.cg.shared.global [%0], [%1], 16;" :: "r"(dst), "l"(src));
}

__device__ __forceinline__ void ldm4(uint32_t* r, uint32_t addr) {
    asm volatile("ldmatrix.sync.aligned.m8n8.x4.shared.b16 {%0,%1,%2,%3}, [%4];"
        : "=r"(r[0]), "=r"(r[1]), "=r"(r[2]), "=r"(r[3]) : "r"(addr));
}

__device__ __forceinline__ void mma_f16(float* c, const uint32_t* a,
                                        uint32_t b0, uint32_t b1) {
    asm volatile(
        "mma.sync.aligned.m16n8k16.row.col.f32.f16.f16.f32 "
        "{%0,%1,%2,%3}, {%4,%5,%6,%7}, {%8,%9}, {%0,%1,%2,%3};"
        : "+f"(c[0]), "+f"(c[1]), "+f"(c[2]), "+f"(c[3])
        : "r"(a[0]), "r"(a[1]), "r"(a[2]), "r"(a[3]), "r"(b0), "r"(b1));
}

__device__ __forceinline__ void split1(float x, __half& h, __half& l) {
    h = __float2half_rn(x);
    l = __float2half_rn(x - __half2float(h));
}

// ---------------------------------------------------------------------------
// fp32 -> (hi, lo) fp16 split, vectorized.
__global__ void __launch_bounds__(256)
split_kernel(const float4* __restrict__ in,
             __half2* __restrict__ h, __half2* __restrict__ l, int n4)
{
    int i = blockIdx.x * blockDim.x + threadIdx.x;
    if (i < n4) {
        float4 v = in[i];
        __half hx, hy, hz, hw, lx, ly, lz, lw;
        split1(v.x, hx, lx); split1(v.y, hy, ly);
        split1(v.z, hz, lz); split1(v.w, hw, lw);
        h[2 * i]     = __halves2half2(hx, hy);
        h[2 * i + 1] = __halves2half2(hz, hw);
        l[2 * i]     = __halves2half2(lx, ly);
        l[2 * i + 1] = __halves2half2(lz, lw);
    }
}

// ---------------------------------------------------------------------------
// Vt[b][d][n] = fp16(V[b][n][d])  (V = qkv cols 2048..3071, reconstructed h+l)
__global__ void __launch_bounds__(256)
transpose_v(const __half* __restrict__ qh, const __half* __restrict__ ql,
            __half* __restrict__ Vth)
{
    __shared__ float t[32][33];
    int b  = blockIdx.z;
    int n0 = blockIdx.x * 32;
    int d0 = blockIdx.y * 32;
    int tx = threadIdx.x, ty = threadIdx.y;   // 32 x 8
    const __half* Vh = qh + (size_t)b * 2048 * 3072 + 2048;
    const __half* Vl = ql + (size_t)b * 2048 * 3072 + 2048;
#pragma unroll
    for (int i = 0; i < 32; i += 8) {
        size_t idx = (size_t)(n0 + ty + i) * 3072 + d0 + tx;
        t[ty + i][tx] = __half2float(Vh[idx]) + __half2float(Vl[idx]);
    }
    __syncthreads();
    __half* dh = Vth + (size_t)b * 1024 * 2048;
#pragma unroll
    for (int i = 0; i < 32; i += 8)
        dh[(size_t)(d0 + ty + i) * 2048 + n0 + tx] = __float2half_rn(t[tx][ty + i]);
}

// ---------------------------------------------------------------------------
// Split NT tensor-core GEMM: C = alpha * A B^T (+bias); A [M,K] (h,l fp16),
// B [N,K] (h[,l]). NT=3: 3-term split; NT=2: A·Bh only (Bl unused).
// Grid (N/BN, M/BM, batch); 256 threads = 8 warps (2 m x 4 n), 64x32 per warp.
// 3-stage cp.async pipeline, one __syncthreads per k-tile.
// smem layout per stage: [Ah][Al][Bh][(Bl)], each 128x64B, XOR-swizzled:
//   16B-chunk' = chunk ^ ((row>>1)&3)   (conflict-free cp.async + ldmatrix)
// ---------------------------------------------------------------------------
template <int NT>
__global__ void __launch_bounds__(256, 2)
gemm_nt_split(const __half* __restrict__ Ah, const __half* __restrict__ Al,
              const __half* __restrict__ Bh, const __half* __restrict__ Bl,
              float* __restrict__ Cf,
              __half* __restrict__ Ch, __half* __restrict__ Cl,
              const float* __restrict__ bias,
              int lda, int ldb, int ldc, int K, float alpha,
              long long sA, long long sB, long long sC)
{
    extern __shared__ char smem[];
    constexpr uint32_t STB = (NT == 3 ? 4u : 3u) * TILE_B;   // stage bytes

    const long long offA = (long long)blockIdx.z * sA;
    const long long offB = (long long)blockIdx.z * sB;
    const long long offC = (long long)blockIdx.z * sC;
    Ah += offA; Al += offA;
    Bh += offB; if (NT == 3) Bl += offB;

    const int tid  = threadIdx.x;
    const int wid  = tid >> 5, lane = tid & 31;
    const int wm   = wid & 1,  wn   = wid >> 1;
    const int g    = lane >> 2, t   = lane & 3;
    const int row0 = blockIdx.y * BM;
    const int col0 = blockIdx.x * BN;

    const uint32_t smem_u = s2u(smem);

    const __half* Abh = Ah + (size_t)row0 * lda;
    const __half* Abl = Al + (size_t)row0 * lda;
    const __half* Bbh = Bh + (size_t)col0 * ldb;
    const __half* Bbl = (NT == 3) ? (Bl + (size_t)col0 * ldb) : nullptr;

    float acc[4][4][4];
#pragma unroll
    for (int i = 0; i < 4; i++)
#pragma unroll
        for (int j = 0; j < 4; j++)
#pragma unroll
            for (int r = 0; r < 4; r++)
                acc[i][j][r] = 0.0f;

    const int nk = K / BK;

    // loader: thread -> rows (tid>>2, +64), 16B chunk (tid&3), swizzled
    const int lr = tid >> 2;
    const int lc = tid & 3;

    auto load_tile = [&](int kb, int s) {
        const uint32_t st = smem_u + (uint32_t)s * STB;
        const int kc = kb * BK + lc * 8;
#pragma unroll
        for (int hh = 0; hh < 2; hh++) {
            const int r = lr + hh * 64;
            const uint32_t phys = (uint32_t)(lc ^ ((r >> 1) & 3));
            const uint32_t off  = (uint32_t)(r * 64) + phys * 16u;
            cp16(st + off,              Abh + (size_t)r * lda + kc);
            cp16(st + TILE_B + off,     Abl + (size_t)r * lda + kc);
            cp16(st + 2 * TILE_B + off, Bbh + (size_t)r * ldb + kc);
            if (NT == 3)
                cp16(st + 3 * TILE_B + off, Bbl + (size_t)r * ldb + kc);
        }
    };

    load_tile(0, 0);
    asm volatile("cp.async.commit_group;");
    load_tile(1, 1);
    asm volatile("cp.async.commit_group;");

    // ldmatrix lane addressing
    const int lrow  = lane & 15;
    const int khalf = lane >> 4;

    int cur = 0;                      // kb % 3
    for (int kb = 0; kb < nk; kb++) {
        if (kb + 1 < nk) asm volatile("cp.async.wait_group 1;");
        else             asm volatile("cp.async.wait_group 0;");
        __syncthreads();

        const uint32_t st = smem_u + (uint32_t)cur * STB;

#pragma unroll
        for (int ks = 0; ks < 2; ks++) {
            uint32_t ah[4][4], al[4][4], bh[2][4], bl[2][4];
#pragma unroll
            for (int i = 0; i < 4; i++) {
                const int row = wm * 64 + i * 16 + lrow;
                const uint32_t phys = (uint32_t)((ks * 2 + khalf) ^ ((row >> 1) & 3));
                const uint32_t ad = st + (uint32_t)(row * 64) + phys * 16u;
                ldm4(ah[i], ad);
                ldm4(al[i], ad + TILE_B);
            }
#pragma unroll
            for (int jp = 0; jp < 2; jp++) {
                const int row = wn * 32 + jp * 16 + lrow;
                const uint32_t phys = (uint32_t)((ks * 2 + khalf) ^ ((row >> 1) & 3));
                const uint32_t bd = st + 2 * TILE_B + (uint32_t)(row * 64) + phys * 16u;
                ldm4(bh[jp], bd);
                if (NT == 3) ldm4(bl[jp], bd + TILE_B);
            }
#pragma unroll
            for (int i = 0; i < 4; i++)
#pragma unroll
                for (int j = 0; j < 4; j++) {
                    const int jp = j >> 1, sjj = j & 1;
                    mma_f16(acc[i][j], ah[i], bh[jp][sjj], bh[jp][sjj + 2]);
                    if (NT == 3)
                        mma_f16(acc[i][j], ah[i], bl[jp][sjj], bl[jp][sjj + 2]);
                    mma_f16(acc[i][j], al[i], bh[jp][sjj], bh[jp][sjj + 2]);
                }
        }

        // prefetch tile kb+2 into the stage consumed at kb-1 (all warps are
        // past it: the barrier above orders iteration kb-1's reads before this)
        if (kb + 2 < nk) {
            const int ls = (cur + 2 >= 3) ? cur - 1 : cur + 2;
            load_tile(kb + 2, ls);
            asm volatile("cp.async.commit_group;");
        }
        cur = (cur + 1 == 3) ? 0 : cur + 1;
    }

    // ---- epilogue
#pragma unroll
    for (int i = 0; i < 4; i++) {
        const int r = row0 + wm * 64 + i * 16 + g;
#pragma unroll
        for (int j = 0; j < 4; j++) {
            const int c = col0 + wn * 32 + j * 8 + 2 * t;
            float v[4];
            v[0] = alpha * acc[i][j][0];
            v[1] = alpha * acc[i][j][1];
            v[2] = alpha * acc[i][j][2];
            v[3] = alpha * acc[i][j][3];
            if (bias) {
                float bx = bias[c], by = bias[c + 1];
                v[0] += bx; v[1] += by; v[2] += bx; v[3] += by;
            }
            if (Cf) {
                *(float2*)(Cf + offC + (size_t)r * ldc + c)       = make_float2(v[0], v[1]);
                *(float2*)(Cf + offC + (size_t)(r + 8) * ldc + c) = make_float2(v[2], v[3]);
            }
            if (Ch) {
                __half h0, l0, h1, l1, h2, l2, h3, l3;
                split1(v[0], h0, l0); split1(v[1], h1, l1);
                split1(v[2], h2, l2); split1(v[3], h3, l3);
                *(__half2*)(Ch + offC + (size_t)r * ldc + c)       = __halves2half2(h0, h1);
                *(__half2*)(Cl + offC + (size_t)r * ldc + c)       = __halves2half2(l0, l1);
                *(__half2*)(Ch + offC + (size_t)(r + 8) * ldc + c) = __halves2half2(h2, h3);
                *(__half2*)(Cl + offC + (size_t)(r + 8) * ldc + c) = __halves2half2(l2, l3);
            }
        }
    }
}

// ---------------------------------------------------------------------------
// Row softmax over 2048-wide rows; writes split fp16 probs.
__global__ void __launch_bounds__(256)
softmax_split(const float* __restrict__ S,
              __half* __restrict__ Sh, __half* __restrict__ Sl)
{
    const size_t base = (size_t)blockIdx.x * 2048;
    const float* row = S + base;
    const int tid = threadIdx.x;

    float v[8];
    float m = -1e30f;
#pragma unroll
    for (int i = 0; i < 8; i++) {
        v[i] = row[tid + 256 * i];
        m = fmaxf(m, v[i]);
    }

    __shared__ float red[8];
#pragma unroll
    for (int o = 16; o; o >>= 1) m = fmaxf(m, __shfl_xor_sync(0xffffffffu, m, o));
    if ((tid & 31) == 0) red[tid >> 5] = m;
    __syncthreads();
    m = red[0];
#pragma unroll
    for (int i = 1; i < 8; i++) m = fmaxf(m, red[i]);
    __syncthreads();

    float s = 0.0f;
#pragma unroll
    for (int i = 0; i < 8; i++) {
        v[i] = __expf(v[i] - m);
        s += v[i];
    }
#pragma unroll
    for (int o = 16; o; o >>= 1) s += __shfl_xor_sync(0xffffffffu, s, o);
    if ((tid & 31) == 0) red[tid >> 5] = s;
    __syncthreads();
    s = 0.0f;
#pragma unroll
    for (int i = 0; i < 8; i++) s += red[i];

    float inv = 1.0f / s;
#pragma unroll
    for (int i = 0; i < 8; i++) {
        float p = v[i] * inv;
        __half h, l;
        split1(p, h, l);
        Sh[base + tid + 256 * i] = h;
        Sl[base + tid + 256 * i] = l;
    }
}

// ---------------------------------------------------------------------------
extern "C" void kernel_launch(void* const* d_in, const int* in_sizes, int n_in,
                              void* d_out, int out_size)
{
    (void)in_sizes; (void)n_in; (void)out_size;
    const float* x     = (const float*)d_in[0];   // [4,2048,1024]
    const float* w_qkv = (const float*)d_in[1];   // [3072,1024]
    const float* w_out = (const float*)d_in[2];   // [1024,1024]
    const float* b_out = (const float*)d_in[3];   // [1024]
    float* out = (float*)d_out;                   // [4,2048,1024]

    float* S;
    __half *xh, *xl, *wqh, *wql, *woh, *wol, *qkvh, *qkvl;
    __half *Sh, *Sl, *Vth, *Oh, *Ol;
    cudaGetSymbolAddress((void**)&S,    g_S);
    cudaGetSymbolAddress((void**)&xh,   g_xh);   cudaGetSymbolAddress((void**)&xl,   g_xl);
    cudaGetSymbolAddress((void**)&wqh,  g_wqh);  cudaGetSymbolAddress((void**)&wql,  g_wql);
    cudaGetSymbolAddress((void**)&woh,  g_woh);  cudaGetSymbolAddress((void**)&wol,  g_wol);
    cudaGetSymbolAddress((void**)&qkvh, g_qkvh); cudaGetSymbolAddress((void**)&qkvl, g_qkvl);
    cudaGetSymbolAddress((void**)&Sh,   g_Sh);   cudaGetSymbolAddress((void**)&Sl,   g_Sl);
    cudaGetSymbolAddress((void**)&Vth,  g_Vth);
    cudaGetSymbolAddress((void**)&Oh,   g_Oh);   cudaGetSymbolAddress((void**)&Ol,   g_Ol);

    const int SM3 = 3 * 4 * TILE_B;   // 98304
    const int SM2 = 3 * 3 * TILE_B;   // 73728
    cudaFuncSetAttribute(gemm_nt_split<3>,
                         cudaFuncAttributeMaxDynamicSharedMemorySize, SM3);
    cudaFuncSetAttribute(gemm_nt_split<2>,
                         cudaFuncAttributeMaxDynamicSharedMemorySize, SM2);

    // 0) split inputs to fp16 (h,l)
    {
        int n4 = 8192 * 1024 / 4;
        split_kernel<<<(n4 + 255) / 256, 256>>>((const float4*)x,
            (__half2*)xh, (__half2*)xl, n4);
        n4 = 3072 * 1024 / 4;
        split_kernel<<<(n4 + 255) / 256, 256>>>((const float4*)w_qkv,
            (__half2*)wqh, (__half2*)wql, n4);
        n4 = 1024 * 1024 / 4;
        split_kernel<<<(n4 + 255) / 256, 256>>>((const float4*)w_out,
            (__half2*)woh, (__half2*)wol, n4);
    }

    // 1) QKV = x @ w_qkv^T : M=8192, N=3072, K=1024 -> split qkv (3-term)
    gemm_nt_split<3><<<dim3(3072 / BN, 8192 / BM, 1), 256, SM3>>>(
        xh, xl, wqh, wql, nullptr, qkvh, qkvl, nullptr,
        1024, 1024, 3072, 1024, 1.0f, 0, 0, 0);

    // 2) S[b] = Q[b] @ K[b]^T * 0.125 : fp32 out (3-term)
    gemm_nt_split<3><<<dim3(2048 / BN, 2048 / BM, 4), 256, SM3>>>(
        qkvh, qkvl, qkvh + 1024, qkvl + 1024, S, nullptr, nullptr, nullptr,
        3072, 3072, 2048, 1024, 0.125f,
        2048ll * 3072, 2048ll * 3072, 2048ll * 2048);

    // 3) softmax -> split fp16 probs
    softmax_split<<<4 * 2048, 256>>>(S, Sh, Sl);

    // 4) Vt[b] = fp16(V[b])^T
    transpose_v<<<dim3(2048 / 32, 1024 / 32, 4), dim3(32, 8)>>>(qkvh, qkvl, Vth);

    // 5) O[b] = P[b] @ V[b] : M=2048, N=1024, K=2048 -> split O (2-term)
    gemm_nt_split<2><<<dim3(1024 / BN, 2048 / BM, 4), 256, SM2>>>(
        Sh, Sl, Vth, nullptr, nullptr, Oh, Ol, nullptr,
        2048, 2048, 1024, 2048, 1.0f,
        2048ll * 2048, 1024ll * 2048, 2048ll * 1024);

    // 6) out = O @ w_out^T + b_out : fp32 out (2-term)
    gemm_nt_split<2><<<dim3(1024 / BN, 8192 / BM, 1), 256, SM2>>>(
        Oh, Ol, woh, nullptr, out, nullptr, nullptr, b_out,
        1024, 1024, 1024, 1024, 1.0f, 0, 0, 0);
}